// round 14
// baseline (speedup 1.0000x reference)
#include <cuda_runtime.h>
#include <cstdint>

// ----------------------------------------------------------------------------
// Problem constants
// ----------------------------------------------------------------------------
#define BS_      1024
#define KTOT     33154
#define HID      512
#define ODIM     129
#define ST_LEN   16641
#define AT_LEN_  129
#define ST1_LEN  16384
#define B_AT     16641      /* st | at boundary   */
#define B_ST1    16770      /* at | st1 boundary  */

#define MT       256        /* CTA tile M (batch)  */
#define NT       128        /* CTA tile N (hidden) */
#define CHUNK    32         /* K per stage         */
#define NCHUNK   1037       /* ceil(33154/32)      */
#define SPLIT    9
#define CPS      116        /* ceil(1037/9)        */

#define A_BYTES  (MT * CHUNK * 4)          /* 32768 */
#define B_BYTES  (NT * CHUNK * 4)          /* 16384 */
#define STAGE    (A_BYTES + B_BYTES)       /* 49152 */
#define SMEM_TOTAL (1024 + 2 * STAGE)      /* 99328 */

// split-K partials: 9 * 1024 * 512 * 4 = 18.9 MB
__device__ float g_partial[SPLIT * BS_ * HID];
// W2 transposed: [129][512] floats
__device__ float g_w2t[ODIM * HID];

// ----------------------------------------------------------------------------
// Helpers (plain-sm_103-safe PTX only: ldmatrix / mma.sync / cvt.rna.tf32)
// ----------------------------------------------------------------------------
__device__ __forceinline__ uint32_t smem_u32(const void* p) {
    uint32_t a;
    asm("{ .reg .u64 t; cvta.to.shared.u64 t, %1; cvt.u32.u64 %0, t; }" : "=r"(a) : "l"(p));
    return a;
}

__device__ __forceinline__ uint32_t swz(uint32_t off) {
    return off ^ ((off >> 3) & 0x70u);
}

__device__ __forceinline__ uint32_t f32_to_tf32(float x) {
    uint32_t r;
    asm("cvt.rna.tf32.f32 %0, %1;" : "=r"(r) : "f"(x));
    return r;
}

__device__ __forceinline__ void ldsm_x4(uint32_t r[4], uint32_t addr) {
    asm volatile("ldmatrix.sync.aligned.m8n8.x4.shared.b16 {%0,%1,%2,%3}, [%4];"
                 : "=r"(r[0]), "=r"(r[1]), "=r"(r[2]), "=r"(r[3]) : "r"(addr));
}

__device__ __forceinline__ void ldsm_x2(uint32_t r[2], uint32_t addr) {
    asm volatile("ldmatrix.sync.aligned.m8n8.x2.shared.b16 {%0,%1}, [%2];"
                 : "=r"(r[0]), "=r"(r[1]) : "r"(addr));
}

__device__ __forceinline__ void mma_tf32(float c[4], const uint32_t a[4], const uint32_t b[2]) {
    asm volatile(
        "mma.sync.aligned.m16n8k8.row.col.f32.tf32.tf32.f32 "
        "{%0,%1,%2,%3}, {%4,%5,%6,%7}, {%8,%9}, {%0,%1,%2,%3};"
        : "+f"(c[0]), "+f"(c[1]), "+f"(c[2]), "+f"(c[3])
        : "r"(a[0]), "r"(a[1]), "r"(a[2]), "r"(a[3]), "r"(b[0]), "r"(b[1]));
}

__device__ __forceinline__ void sts32(uint32_t addr, uint32_t v) {
    asm volatile("st.shared.b32 [%0], %1;" :: "r"(addr), "r"(v));
}
__device__ __forceinline__ void sts128(uint32_t addr, uint32_t v0, uint32_t v1, uint32_t v2, uint32_t v3) {
    asm volatile("st.shared.v4.b32 [%0], {%1,%2,%3,%4};" :: "r"(addr), "r"(v0), "r"(v1), "r"(v2), "r"(v3));
}

// ----------------------------------------------------------------------------
// GEMM1: H_partial = X @ W1, tf32 mma.sync, split-K=9.
// grid = 144 CTAs = 4 nt x 4 mt x 9 split, 256 threads (8 warps).
// SMEM per stage: A [256 m][32 k], B [128 n][32 k], 128B rows, SW128 swizzle.
// Warp tile 64(M) x 64(N): wm = w>>1, wn = w&1.   (proven round-4 structure)
// ----------------------------------------------------------------------------
__global__ void __launch_bounds__(256, 1) gemm1_kernel(
    const float* __restrict__ st, const float* __restrict__ at,
    const float* __restrict__ st1, const float* __restrict__ W1)
{
    extern __shared__ char smem_raw[];
    uint32_t base = smem_u32(smem_raw);
    base = (base + 1023u) & ~1023u;

    const int tid = threadIdx.x;
    const int l   = tid & 31;
    const int w   = tid >> 5;
    const int wm  = w >> 1;       // 0..3
    const int wn  = w & 1;        // 0..1

    const int bx = blockIdx.x;
    const int nt = bx & 3;
    const int mt = (bx >> 2) & 3;
    const int sp = bx >> 4;       // 0..8

    const int c0  = sp * CPS;
    int nch = NCHUNK - c0;
    if (nch > CPS) nch = CPS;

    const int mbase = mt * MT + w * 32;
    const int bg = w & 3;                 // B n-group (32 n each)
    const int bh = w >> 2;                // B k-half  (16 k each)
    const int bn = nt * NT + bg * 32 + l; // global n for B fill

    // ---- chunk load (GMEM -> regs, with rna tf32 rounding) ----
    auto load_chunk = [&](int chunk, uint32_t aPre[32], uint32_t bPre[16]) {
        const int k0 = chunk * CHUNK;
        const int kk = k0 + l;
        const float* src = 0; int stride = 0;
        if (kk < B_AT)          { src = st  + kk;            stride = ST_LEN;  }
        else if (kk < B_ST1)    { src = at  + (kk - B_AT);   stride = AT_LEN_; }
        else if (kk < KTOT)     { src = st1 + (kk - B_ST1);  stride = ST1_LEN; }
#pragma unroll
        for (int r = 0; r < 32; ++r) {
            float v = src ? __ldg(src + (size_t)(mbase + r) * stride) : 0.0f;
            aPre[r] = f32_to_tf32(v);
        }
#pragma unroll
        for (int j = 0; j < 16; ++j) {
            const int k = k0 + bh * 16 + j;
            float v = (k < KTOT) ? __ldg(W1 + (size_t)k * HID + bn) : 0.0f;
            bPre[j] = f32_to_tf32(v);
        }
    };

    // ---- chunk store (regs -> SMEM, swizzled) ----
    auto store_chunk = [&](int s, const uint32_t aPre[32], const uint32_t bPre[16]) {
        const uint32_t Ab = base + (uint32_t)s * STAGE;
        const uint32_t Bb = Ab + A_BYTES;
#pragma unroll
        for (int r = 0; r < 32; ++r)
            sts32(Ab + swz((uint32_t)((w * 32 + r) * 128 + l * 4)), aPre[r]);
#pragma unroll
        for (int j4 = 0; j4 < 4; ++j4) {
            const uint32_t off = swz((uint32_t)((bg * 32 + l) * 128 + (bh * 16 + j4 * 4) * 4));
            sts128(Bb + off, bPre[j4 * 4], bPre[j4 * 4 + 1], bPre[j4 * 4 + 2], bPre[j4 * 4 + 3]);
        }
    };

    // ---- fragment smem offsets (pre-swizzle, in-tile) ----
    uint32_t relA[4], relB[8];
#pragma unroll
    for (int t = 0; t < 4; ++t)
        relA[t] = (uint32_t)((wm * 64 + t * 16 + (l & 7) + ((l >> 3) & 1) * 8) * 128
                             + ((l >> 4) & 1) * 16);
    const int lm = l & 15;
#pragma unroll
    for (int u = 0; u < 8; ++u)
        relB[u] = (uint32_t)((wn * 64 + u * 8 + (lm & 7)) * 128 + ((lm >> 3) & 1) * 16);

    float acc[4][8][4];
#pragma unroll
    for (int t = 0; t < 4; ++t)
#pragma unroll
        for (int u = 0; u < 8; ++u)
#pragma unroll
            for (int j = 0; j < 4; ++j) acc[t][u][j] = 0.0f;

    // ---- prologue ----
    {
        uint32_t aPre[32], bPre[16];
        load_chunk(c0, aPre, bPre);
        store_chunk(0, aPre, bPre);
    }
    __syncthreads();

    // ---- main loop ----
    for (int i = 0; i < nch; ++i) {
        const int s = i & 1;
        const uint32_t Ab = base + (uint32_t)s * STAGE;
        const uint32_t Bb = Ab + A_BYTES;

        uint32_t aPre[32], bPre[16];
        const bool pf = (i + 1 < nch);
        if (pf) load_chunk(c0 + i + 1, aPre, bPre);

#pragma unroll
        for (int ks = 0; ks < 4; ++ks) {
            uint32_t afr[4][4], bfr[8][2];
#pragma unroll
            for (int t = 0; t < 4; ++t) ldsm_x4(afr[t], Ab + swz(relA[t] + ks * 32));
#pragma unroll
            for (int u = 0; u < 8; ++u) ldsm_x2(bfr[u], Bb + swz(relB[u] + ks * 32));
#pragma unroll
            for (int t = 0; t < 4; ++t)
#pragma unroll
                for (int u = 0; u < 8; ++u)
                    mma_tf32(acc[t][u], afr[t], bfr[u]);
        }

        if (pf) store_chunk(s ^ 1, aPre, bPre);
        __syncthreads();
    }

    // ---- epilogue: write split-K partials ----
    float* outp = g_partial + (size_t)sp * BS_ * HID;
#pragma unroll
    for (int t = 0; t < 4; ++t) {
        const int row0 = mt * MT + wm * 64 + t * 16 + (l >> 2);
#pragma unroll
        for (int u = 0; u < 8; ++u) {
            const int col = nt * NT + wn * 64 + u * 8 + (l & 3) * 2;
            float2 v0; v0.x = acc[t][u][0]; v0.y = acc[t][u][1];
            float2 v1; v1.x = acc[t][u][2]; v1.y = acc[t][u][3];
            *(float2*)(outp + (size_t)row0 * HID + col)       = v0;
            *(float2*)(outp + (size_t)(row0 + 8) * HID + col) = v1;
        }
    }
}

// ----------------------------------------------------------------------------
// W2 transpose: [512][129] -> W2T [129][512] (float4-loadable rows)
// ----------------------------------------------------------------------------
__global__ void __launch_bounds__(256) transpose_w2_kernel(const float* __restrict__ W2)
{
    __shared__ float tile[32][33];
    const int j0 = blockIdx.x * 32;
    const int k0 = blockIdx.y * 32;

#pragma unroll
    for (int i = threadIdx.y; i < 32; i += 8) {
        const int k = k0 + i;
        const int j = j0 + threadIdx.x;
        tile[i][threadIdx.x] = (j < ODIM) ? __ldg(W2 + (size_t)k * ODIM + j) : 0.0f;
    }
    __syncthreads();

    const int k = k0 + threadIdx.x;
#pragma unroll
    for (int i = threadIdx.y; i < 32; i += 8) {
        const int j = j0 + i;
        if (j < ODIM) g_w2t[(size_t)j * HID + k] = tile[threadIdx.x][i];
    }
}

// ----------------------------------------------------------------------------
// Kernel 2: reduce split-K partials + b1 + ReLU, then H @ W2T + b2.
// grid = 256 CTAs x 512 threads; 4 batch rows per CTA.
// ----------------------------------------------------------------------------
__global__ void __launch_bounds__(512) mlp2_kernel(
    const float* __restrict__ b1, const float* __restrict__ b2,
    float* __restrict__ out)
{
    __shared__ float h_s[4 * HID];   // 8 KB
    const int tid = threadIdx.x;
    const int row0 = blockIdx.x * 4;

    // Phase 1: 4 rows x 128 float4 = 512 float4 -> exactly 1 per thread
    {
        const int r  = tid >> 7;
        const int c4 = tid & 127;
        float4 s = __ldg((const float4*)b1 + c4);
#pragma unroll
        for (int sp = 0; sp < SPLIT; ++sp) {
            float4 p = *((const float4*)g_partial +
                         ((size_t)sp * BS_ + (row0 + r)) * (HID / 4) + c4);
            s.x += p.x; s.y += p.y; s.z += p.z; s.w += p.w;
        }
        float4* dst = (float4*)h_s + r * (HID / 4) + c4;
        dst->x = fmaxf(s.x, 0.0f); dst->y = fmaxf(s.y, 0.0f);
        dst->z = fmaxf(s.z, 0.0f); dst->w = fmaxf(s.w, 0.0f);
    }
    __syncthreads();

    // Phase 2: 4*129 = 516 dots; W2T rows read as float4 (L2-resident)
    for (int d = tid; d < 4 * ODIM; d += 512) {
        const int r = d / ODIM;
        const int j = d - r * ODIM;
        const float4* wp = (const float4*)(g_w2t + (size_t)j * HID);
        const float4* hp = (const float4*)(h_s + r * HID);
        float a0 = 0.f, a1 = 0.f, a2 = 0.f, a3 = 0.f;
#pragma unroll 8
        for (int k4 = 0; k4 < HID / 4; ++k4) {
            const float4 wv = __ldg(wp + k4);
            const float4 hv = hp[k4];
            a0 = fmaf(wv.x, hv.x, a0);
            a1 = fmaf(wv.y, hv.y, a1);
            a2 = fmaf(wv.z, hv.z, a2);
            a3 = fmaf(wv.w, hv.w, a3);
        }
        out[(size_t)row0 * ODIM + d] = (a0 + a1) + (a2 + a3) + __ldg(b2 + j);
    }
}

// ----------------------------------------------------------------------------
// Launch
// ----------------------------------------------------------------------------
extern "C" void kernel_launch(void* const* d_in, const int* in_sizes, int n_in,
                              void* d_out, int out_size) {
    const float* st  = (const float*)d_in[0];
    const float* at  = (const float*)d_in[1];
    const float* st1 = (const float*)d_in[2];
    const float* W1  = (const float*)d_in[3];
    const float* b1  = (const float*)d_in[4];
    const float* W2  = (const float*)d_in[5];
    const float* b2  = (const float*)d_in[6];
    float* out = (float*)d_out;

    cudaFuncSetAttribute(gemm1_kernel, cudaFuncAttributeMaxDynamicSharedMemorySize, SMEM_TOTAL);

    dim3 tgrid(5, 16);
    dim3 tblk(32, 8);
    transpose_w2_kernel<<<tgrid, tblk>>>(W2);
    gemm1_kernel<<<144, 256, SMEM_TOTAL>>>(st, at, st1, W1);
    mlp2_kernel<<<BS_ / 4, 512>>>(b1, b2, out);
}